// round 16
// baseline (speedup 1.0000x reference)
#include <cuda_runtime.h>
#include <cstdint>
#include <cstddef>

// ----------------------------------------------------------------------------
// Round 16 = R13 base, with:
//  (1) cluster barrier REPLACED by warp-granular DSMEM flag sync:
//      producer lanes: stcg partial -> red.release.cluster +1 into 3 peers'
//      flag[crank][row]; consumer warp polls its 3 peer flags (>= 32*(t+1)).
//      No UCGABAR, no CTA-wide convergence in the tail.
//  (2) own-rank partial kept in registers (myp) -> 3-way publish/fold only.
//  (3) G2 weight pair-hoisting (halves weight crossbar traffic).
//  (4) pairwise-tree combines in C1/C2.
//   a <- a + W2^T tanh([x_t; a] @ W1 + b1) + b2,  512 steps.
// 32 clusters x 4 CTAs; cluster owns 8 batch rows; CTA rank owns hidden slice
// [128r, 128r+128). G1 weights in registers (w1x[16]+w1a[16] ulonglong2/thread).
// ----------------------------------------------------------------------------

#define T_STEPS  512
#define DIN      128
#define DST      128
#define DHID     512
#define NCL      32
#define CSZ      4
#define ROWS     8
#define NTHREADS 256

typedef unsigned long long u64;

#define FMA2(acc, s, w) asm("fma.rn.f32x2 %0, %1, %2, %0;" : "+l"(acc) : "l"(s), "l"(w))
#define PACK2(d, v)     asm("mov.b64 %0, {%1, %1};"        : "=l"(d)   : "r"(__float_as_uint(v)))

// double-buffered per-rank partial states (1 MB static scratch)
__device__ float g_pstate[2][NCL][CSZ][ROWS][DST];

// smem layout (floats):
//   W2s  [128][128] @ 0      (64KB)
//   hp   [8][8][128]@ 16384  (32KB)  G2 partials
//   hp_x [8][8][128]@ 24576  (32KB)  G1x partials, then G1a-accumulated preacts
//   a_s  [8][128]   @ 32768  ( 4KB)
//   x2   [2][8][128]@ 33792  ( 8KB)  double-buffered x
//   h_s  [8][128]   @ 35840  ( 4KB)
//   flags[4][8] u32 @ 36864  (128B)  per-(rank,row) monotonic counters
#define OFF_HP   16384
#define OFF_HPX  24576
#define OFF_AS   32768
#define OFF_X2   33792
#define OFF_HS   35840
#define OFF_FLG  36864
#define SMEM_FLOATS 36896    // 147584 B

static __device__ __forceinline__ float4 f4add(float4 a, float4 b) {
    return make_float4(a.x + b.x, a.y + b.y, a.z + b.z, a.w + b.w);
}

// tanh(x) = 1 - 2/(e^{2x}+1) via ex2.approx/rcp.approx. Abs err ~1e-7.
static __device__ __forceinline__ float tanh_fast(float v) {
    float e, r;
    asm("ex2.approx.f32 %0, %1;" : "=f"(e) : "f"(v * 2.8853900817779268f));
    asm("rcp.approx.f32 %0, %1;" : "=f"(r) : "f"(e + 1.0f));
    return fmaf(-2.0f, r, 1.0f);
}

// 16-k x 4-row x 4-col GEMM partial with register weights (fresh write).
static __device__ __forceinline__ void gemm16_rows(
    const float* __restrict__ act, const ulonglong2* __restrict__ w,
    float* __restrict__ outp, int rlo)
{
    ulonglong2 acc[4];
    #pragma unroll
    for (int r = 0; r < 4; ++r) { acc[r].x = 0ull; acc[r].y = 0ull; }
    #pragma unroll
    for (int kb = 0; kb < 4; ++kb) {
        float4 av[4];
        #pragma unroll
        for (int r = 0; r < 4; ++r)
            av[r] = *(const float4*)(act + (rlo + r) * 128 + kb * 4);
        #pragma unroll
        for (int kk = 0; kk < 4; ++kk) {
            const ulonglong2 ww = w[kb * 4 + kk];
            #pragma unroll
            for (int r = 0; r < 4; ++r) {
                float s = (kk == 0) ? av[r].x : (kk == 1) ? av[r].y
                        : (kk == 2) ? av[r].z : av[r].w;
                u64 sp; PACK2(sp, s);
                FMA2(acc[r].x, sp, ww.x);
                FMA2(acc[r].y, sp, ww.y);
            }
        }
    }
    #pragma unroll
    for (int r = 0; r < 4; ++r)
        *(ulonglong2*)(outp + (rlo + r) * 128) = acc[r];
}

// Same, accumulating on top of existing buffer contents (G1x partials).
static __device__ __forceinline__ void gemm16_rows_acc(
    const float* __restrict__ act, const ulonglong2* __restrict__ w,
    float* __restrict__ outp, int rlo)
{
    ulonglong2 acc[4];
    #pragma unroll
    for (int r = 0; r < 4; ++r)
        acc[r] = *(const ulonglong2*)(outp + (rlo + r) * 128);
    #pragma unroll
    for (int kb = 0; kb < 4; ++kb) {
        float4 av[4];
        #pragma unroll
        for (int r = 0; r < 4; ++r)
            av[r] = *(const float4*)(act + (rlo + r) * 128 + kb * 4);
        #pragma unroll
        for (int kk = 0; kk < 4; ++kk) {
            const ulonglong2 ww = w[kb * 4 + kk];
            #pragma unroll
            for (int r = 0; r < 4; ++r) {
                float s = (kk == 0) ? av[r].x : (kk == 1) ? av[r].y
                        : (kk == 2) ? av[r].z : av[r].w;
                u64 sp; PACK2(sp, s);
                FMA2(acc[r].x, sp, ww.x);
                FMA2(acc[r].y, sp, ww.y);
            }
        }
    }
    #pragma unroll
    for (int r = 0; r < 4; ++r)
        *(ulonglong2*)(outp + (rlo + r) * 128) = acc[r];
}

__global__ void __cluster_dims__(CSZ, 1, 1) __launch_bounds__(NTHREADS, 1)
rnn_kernel(const float* __restrict__ x,  const float* __restrict__ a0,
           const float* __restrict__ W1, const float* __restrict__ b1,
           const float* __restrict__ W2, const float* __restrict__ b2,
           float* __restrict__ out)
{
    extern __shared__ float sm[];
    float* W2s  = sm;
    float* hp   = sm + OFF_HP;
    float* hp_x = sm + OFF_HPX;
    float* a_s  = sm + OFF_AS;
    float* x2   = sm + OFF_X2;   // [2][8][128]
    float* h_s  = sm + OFF_HS;

    uint32_t smem_u32;
    asm("{ .reg .u64 t; cvta.to.shared.u64 t, %1; cvt.u32.u64 %0, t; }"
        : "=r"(smem_u32) : "l"(sm));

    const int tid   = threadIdx.x;
    const int lane  = tid & 31;
    const int wid   = tid >> 5;
    const int bx    = blockIdx.x;
    const int crank = bx & (CSZ - 1);
    const int gcl   = bx >> 2;
    const int rowbase = gcl * ROWS;
    const int jbase   = crank * 128;
    const int cj      = lane * 4;

    // ---- G1 weights into registers ----
    ulonglong2 w1x[16], w1a[16];
    {
        const float* ws = W1 + (size_t)(16 * wid) * DHID + jbase + cj;
        #pragma unroll
        for (int r = 0; r < 16; ++r)
            w1x[r] = *(const ulonglong2*)(ws + (size_t)r * DHID);
        const float* wa = W1 + (size_t)(128 + 16 * wid) * DHID + jbase + cj;
        #pragma unroll
        for (int r = 0; r < 16; ++r)
            w1a[r] = *(const ulonglong2*)(wa + (size_t)r * DHID);
    }

    // ---- prologue: W2 slice, a0, x(0)->x2[0]; zero flags ----
    for (int i = tid; i < 4096; i += NTHREADS)
        ((float4*)W2s)[i] = ((const float4*)(W2 + (size_t)jbase * DST))[i];
    for (int i = tid; i < 256; i += NTHREADS)
        ((float4*)a_s)[i] = ((const float4*)(a0 + (size_t)rowbase * DST))[i];
    for (int i = tid; i < 256; i += NTHREADS) {
        int r = i >> 5, c4 = (i & 31) << 2;
        *(float4*)(x2 + r * 128 + c4) =
            *(const float4*)(x + (size_t)(rowbase + r) * (size_t)(T_STEPS * DIN) + c4);
    }
    if (tid < CSZ * ROWS)
        ((volatile unsigned*)(sm + OFF_FLG))[tid] = 0u;

    const int crow = wid;                 // this warp's batch row
    const float4 rb1 = *(const float4*)(b1 + jbase + cj);
    const float4 rb2 = *(const float4*)(b2 + cj);

    // flag addresses: my slot (crank, crow) mapped into each of the 3 peers;
    // and the 3 local slots I poll (peer rank r, row crow).
    const int p0r = (crank + 1) & 3, p1r = (crank + 2) & 3, p2r = (crank + 3) & 3;
    const uint32_t my_flag_local = smem_u32 + OFF_FLG * 4 + (crank * ROWS + crow) * 4;
    uint32_t ra0, ra1, ra2;
    asm("mapa.shared::cluster.u32 %0, %1, %2;" : "=r"(ra0) : "r"(my_flag_local), "r"(p0r));
    asm("mapa.shared::cluster.u32 %0, %1, %2;" : "=r"(ra1) : "r"(my_flag_local), "r"(p1r));
    asm("mapa.shared::cluster.u32 %0, %1, %2;" : "=r"(ra2) : "r"(my_flag_local), "r"(p2r));
    const uint32_t fa0 = smem_u32 + OFF_FLG * 4 + (p0r * ROWS + crow) * 4;
    const uint32_t fa1 = smem_u32 + OFF_FLG * 4 + (p1r * ROWS + crow) * 4;
    const uint32_t fa2 = smem_u32 + OFF_FLG * 4 + (p2r * ROWS + crow) * 4;

    const float* xrow = x + (size_t)(rowbase + crow) * (size_t)(T_STEPS * DIN) + cj;
    *(float4*)(x2 + 1024 + crow * 128 + cj) = *(const float4*)(xrow + DIN);  // x(1)
    float4 xr = *(const float4*)(xrow + 2 * DIN);                            // x(2)

    const float* g2_wr = W2s + (wid * 16) * 128 + cj;
    float* hpo  = hp   + wid * 1024 + cj;
    float* hpxo = hp_x + wid * 1024 + cj;

    __syncthreads();
    // one-time cluster convergence: all flags zeroed before any remote red
    asm volatile("barrier.cluster.arrive.aligned;" ::: "memory");
    asm volatile("barrier.cluster.wait.aligned;"   ::: "memory");

    // ---- G1x for step 0 ----
    gemm16_rows(x2 + wid * 16, w1x, hpxo, 0);
    gemm16_rows(x2 + wid * 16, w1x, hpxo, 4);
    __syncthreads();   // B1 (step 0 entry)

    float4 myp = make_float4(0.f, 0.f, 0.f, 0.f);

    for (int t = 0; t < T_STEPS; ++t) {
        // ---- G1a: accumulate a-part on top of G1x partials in hp_x ----
        gemm16_rows_acc(a_s + wid * 16, w1a, hpxo, 0);
        gemm16_rows_acc(a_s + wid * 16, w1a, hpxo, 4);
        __syncthreads();   // B2

        // ---- C1: preact = tree-sum(8 hp_x bufs) + b1 -> tanh_fast -> h_s ----
        {
            const float* hbx = hp_x + crow * 128 + cj;
            float4 s01 = f4add(*(const float4*)(hbx),
                               *(const float4*)(hbx + 1024));
            float4 s23 = f4add(*(const float4*)(hbx + 2048),
                               *(const float4*)(hbx + 3072));
            float4 s45 = f4add(*(const float4*)(hbx + 4096),
                               *(const float4*)(hbx + 5120));
            float4 s67 = f4add(*(const float4*)(hbx + 6144),
                               *(const float4*)(hbx + 7168));
            float4 s = f4add(f4add(s01, s23), f4add(s45, s67));
            float4 hv;
            hv.x = tanh_fast(s.x + rb1.x);
            hv.y = tanh_fast(s.y + rb1.y);
            hv.z = tanh_fast(s.z + rb1.z);
            hv.w = tanh_fast(s.w + rb1.w);
            *(float4*)(h_s + crow * 128 + cj) = hv;
        }
        __syncthreads();   // B3

        // ---- G2: warp = 16-j chunk x 8 rows; weights pair-hoisted ----
        {
            ulonglong2 acc[ROWS];
            #pragma unroll
            for (int r = 0; r < ROWS; ++r) { acc[r].x = 0ull; acc[r].y = 0ull; }
            const float* act2 = h_s + wid * 16;
            #pragma unroll
            for (int kb = 0; kb < 4; ++kb) {
                const float* wk = g2_wr + kb * 4 * 128;
                #pragma unroll
                for (int pr = 0; pr < 2; ++pr) {
                    const ulonglong2 wwa = *(const ulonglong2*)(wk + (pr * 2 + 0) * 128);
                    const ulonglong2 wwb = *(const ulonglong2*)(wk + (pr * 2 + 1) * 128);
                    #pragma unroll
                    for (int half = 0; half < 2; ++half) {
                        float2 av[4];
                        #pragma unroll
                        for (int r = 0; r < 4; ++r)
                            av[r] = *(const float2*)(act2 + (half * 4 + r) * 128
                                                     + kb * 4 + pr * 2);
                        #pragma unroll
                        for (int r = 0; r < 4; ++r) {
                            u64 s0, s1;
                            PACK2(s0, av[r].x);
                            PACK2(s1, av[r].y);
                            FMA2(acc[half * 4 + r].x, s0, wwa.x);
                            FMA2(acc[half * 4 + r].y, s0, wwa.y);
                            FMA2(acc[half * 4 + r].x, s1, wwb.x);
                            FMA2(acc[half * 4 + r].y, s1, wwb.y);
                        }
                    }
                }
            }
            #pragma unroll
            for (int r = 0; r < ROWS; ++r)
                *(ulonglong2*)(hpo + r * 128) = acc[r];
        }
        __syncthreads();   // B4

        // ---- C2: tree-combine 8 G2 bufs -> myp; publish to 3 peers; flag ----
        {
            const float* hb = hp + crow * 128 + cj;
            float4 s01 = f4add(*(const float4*)(hb),
                               *(const float4*)(hb + 1024));
            float4 s23 = f4add(*(const float4*)(hb + 2048),
                               *(const float4*)(hb + 3072));
            float4 s45 = f4add(*(const float4*)(hb + 4096),
                               *(const float4*)(hb + 5120));
            float4 s67 = f4add(*(const float4*)(hb + 6144),
                               *(const float4*)(hb + 7168));
            myp = f4add(f4add(s01, s23), f4add(s45, s67));
            __stcg((float4*)&g_pstate[t & 1][gcl][crank][crow][cj], myp);
            // each lane's release-red orders ITS OWN stcg before the count tick
            asm volatile("red.release.cluster.shared::cluster.add.u32 [%0], 1;"
                         :: "r"(ra0) : "memory");
            asm volatile("red.release.cluster.shared::cluster.add.u32 [%0], 1;"
                         :: "r"(ra1) : "memory");
            asm volatile("red.release.cluster.shared::cluster.add.u32 [%0], 1;"
                         :: "r"(ra2) : "memory");
        }

        // ---- G1x(t+1) part A: rows 0-3, hides publish/flag flight time ----
        const float* xb = x2 + ((t + 1) & 1) * 1024 + wid * 16;
        if (t + 1 < T_STEPS)
            gemm16_rows(xb, w1x, hpxo, 0);

        // ---- poll the 3 peer flags for step t (warp-granular sync) ----
        {
            const unsigned tgt = 32u * (unsigned)(t + 1);
            unsigned f0, f1, f2;
            do {
                asm volatile("ld.volatile.shared.u32 %0, [%1];" : "=r"(f0) : "r"(fa0) : "memory");
                asm volatile("ld.volatile.shared.u32 %0, [%1];" : "=r"(f1) : "r"(fa1) : "memory");
                asm volatile("ld.volatile.shared.u32 %0, [%1];" : "=r"(f2) : "r"(fa2) : "memory");
            } while (f0 < tgt || f1 < tgt || f2 < tgt);
        }

        // ---- fold loads (in-order issue after poll), hidden under G1x B ----
        float4 p0 = __ldcg((const float4*)&g_pstate[t & 1][gcl][p0r][crow][cj]);
        float4 p1 = __ldcg((const float4*)&g_pstate[t & 1][gcl][p1r][crow][cj]);
        float4 p2 = __ldcg((const float4*)&g_pstate[t & 1][gcl][p2r][crow][cj]);

        if (t + 1 < T_STEPS)
            gemm16_rows(xb, w1x, hpxo, 4);

        // ---- fold combine: a(t+1) = a(t) + myp + 3 peers + b2 ----
        {
            float4 acc = f4add(f4add(p0, p1), f4add(p2, myp));
            float4 av = *(float4*)(a_s + crow * DST + cj);
            av.x += acc.x + rb2.x;  av.y += acc.y + rb2.y;
            av.z += acc.z + rb2.z;  av.w += acc.w + rb2.w;
            *(float4*)(a_s + crow * DST + cj) = av;
        }
        // ---- stage x(t+2); prefetch x(t+3) ----
        if (t + 2 < T_STEPS) {
            *(float4*)(x2 + (t & 1) * 1024 + crow * 128 + cj) = xr;
            if (t + 3 < T_STEPS)
                xr = *(const float4*)(xrow + (size_t)(t + 3) * DIN);
        }
        __syncthreads();   // B1
    }

    // ---- epilogue: a_s holds a(T); rank 0 writes out ----
    if (crank == 0) {
        float4 av = *(float4*)(a_s + crow * DST + cj);
        *(float4*)(out + (size_t)(rowbase + crow) * DST + cj) = av;
    }
    // no CTA may exit while peers can still target its SMEM (flags)
    asm volatile("barrier.cluster.arrive.aligned;" ::: "memory");
    asm volatile("barrier.cluster.wait.aligned;"   ::: "memory");
}

extern "C" void kernel_launch(void* const* d_in, const int* in_sizes, int n_in,
                              void* d_out, int out_size) {
    const float* x  = (const float*)d_in[0];
    const float* a0 = (const float*)d_in[1];
    const float* W1 = (const float*)d_in[2];
    const float* b1 = (const float*)d_in[3];
    const float* W2 = (const float*)d_in[4];
    const float* b2 = (const float*)d_in[5];
    float* out = (float*)d_out;

    const size_t smem = SMEM_FLOATS * sizeof(float);   // 147584 B
    cudaFuncSetAttribute(rnn_kernel, cudaFuncAttributeMaxDynamicSharedMemorySize,
                         (int)smem);
    rnn_kernel<<<NCL * CSZ, NTHREADS, smem>>>(x, a0, W1, b1, W2, b2, out);
}

// round 17
// speedup vs baseline: 1.5125x; 1.5125x over previous
#include <cuda_runtime.h>
#include <cstdint>
#include <cstddef>

// ----------------------------------------------------------------------------
// Round 17 = R13 (best, 1764us) + correctly-padded C1-merge (removes B3)
//            + G2 weight-load hoisting (av[8] staging).
//   a <- a + W2^T tanh([x_t; a] @ W1 + b1) + b2,  512 steps.
// 32 clusters x 4 CTAs; cluster owns 8 batch rows; CTA rank owns hidden slice
// [128r, 128r+128). G1 weights in registers (w1x[16]+w1a[16] ulonglong2/thread).
//
// Pad rule: hp_x and h_s rows are 136 floats so the C1-j lane map (r8, j4)
// hits 16B-groups (2*r8 + j4) mod 8 -> uniform multiplicity 4 (conflict-free
// wavefronts). hp stays 128 (C2 reads are lane-consecutive).
//
// Per-step: G1a(acc into hp_x) | B2 |
//   [C1-j: lane=(row,j4) tree-sums 8 hp_x bufs + b1, tanh -> h_s own chunk;
//    __syncwarp; G2: same warp contracts its j-chunk, weights LDS'd once] |
//   B4 | C2(tree combine, publish .cg) | cluster.arrive |
//   G1x(t+1) rows 0-3 | cluster.wait | fold ldcg x4 | G1x(t+1) rows 4-7 |
//   fold combine + x stage | B1
// ----------------------------------------------------------------------------

#define T_STEPS  512
#define DIN      128
#define DST      128
#define DHID     512
#define NCL      32
#define CSZ      4
#define ROWS     8
#define NTHREADS 256

#define HPX  136      // hp_x / h_s row stride (floats)
#define HBX  1088     // 8 * HPX: one hp_x buffer

typedef unsigned long long u64;

#define FMA2(acc, s, w) asm("fma.rn.f32x2 %0, %1, %2, %0;" : "+l"(acc) : "l"(s), "l"(w))
#define PACK2(d, v)     asm("mov.b64 %0, {%1, %1};"        : "=l"(d)   : "r"(__float_as_uint(v)))

// double-buffered per-rank partial states (1 MB static scratch)
__device__ float g_pstate[2][NCL][CSZ][ROWS][DST];

// smem layout (floats):
//   W2s  [128][128]  @ 0      (65536 B)
//   hp   [8][8][128] @ 16384  (32768 B)  G2 partials (stride 128)
//   hp_x [8][8][136] @ 24576  (34816 B)  G1x+G1a preact partials (stride 136)
//   a_s  [8][128]    @ 33280  ( 4096 B)
//   x2   [2][8][128] @ 34304  ( 8192 B)
//   h_s  [8][136]    @ 36352  ( 4352 B)  (stride 136)
#define OFF_HP   16384
#define OFF_HPX  24576
#define OFF_AS   33280
#define OFF_X2   34304
#define OFF_HS   36352
#define SMEM_FLOATS 37440    // 149760 B

static __device__ __forceinline__ float4 f4add(float4 a, float4 b) {
    return make_float4(a.x + b.x, a.y + b.y, a.z + b.z, a.w + b.w);
}

// tanh(x) = 1 - 2/(e^{2x}+1) via ex2.approx/rcp.approx. Abs err ~1e-7.
static __device__ __forceinline__ float tanh_fast(float v) {
    float e, r;
    asm("ex2.approx.f32 %0, %1;" : "=f"(e) : "f"(v * 2.8853900817779268f));
    asm("rcp.approx.f32 %0, %1;" : "=f"(r) : "f"(e + 1.0f));
    return fmaf(-2.0f, r, 1.0f);
}

// 16-k x 4-row x 4-col GEMM partial, register weights, fresh write.
// act rows stride 128; out rows stride HPX.
static __device__ __forceinline__ void gemm16_rows(
    const float* __restrict__ act, const ulonglong2* __restrict__ w,
    float* __restrict__ outp, int rlo)
{
    ulonglong2 acc[4];
    #pragma unroll
    for (int r = 0; r < 4; ++r) { acc[r].x = 0ull; acc[r].y = 0ull; }
    #pragma unroll
    for (int kb = 0; kb < 4; ++kb) {
        float4 av[4];
        #pragma unroll
        for (int r = 0; r < 4; ++r)
            av[r] = *(const float4*)(act + (rlo + r) * 128 + kb * 4);
        #pragma unroll
        for (int kk = 0; kk < 4; ++kk) {
            const ulonglong2 ww = w[kb * 4 + kk];
            #pragma unroll
            for (int r = 0; r < 4; ++r) {
                float s = (kk == 0) ? av[r].x : (kk == 1) ? av[r].y
                        : (kk == 2) ? av[r].z : av[r].w;
                u64 sp; PACK2(sp, s);
                FMA2(acc[r].x, sp, ww.x);
                FMA2(acc[r].y, sp, ww.y);
            }
        }
    }
    #pragma unroll
    for (int r = 0; r < 4; ++r)
        *(ulonglong2*)(outp + (rlo + r) * HPX) = acc[r];
}

// Same, accumulating on top of existing buffer contents (G1x partials).
static __device__ __forceinline__ void gemm16_rows_acc(
    const float* __restrict__ act, const ulonglong2* __restrict__ w,
    float* __restrict__ outp, int rlo)
{
    ulonglong2 acc[4];
    #pragma unroll
    for (int r = 0; r < 4; ++r)
        acc[r] = *(const ulonglong2*)(outp + (rlo + r) * HPX);
    #pragma unroll
    for (int kb = 0; kb < 4; ++kb) {
        float4 av[4];
        #pragma unroll
        for (int r = 0; r < 4; ++r)
            av[r] = *(const float4*)(act + (rlo + r) * 128 + kb * 4);
        #pragma unroll
        for (int kk = 0; kk < 4; ++kk) {
            const ulonglong2 ww = w[kb * 4 + kk];
            #pragma unroll
            for (int r = 0; r < 4; ++r) {
                float s = (kk == 0) ? av[r].x : (kk == 1) ? av[r].y
                        : (kk == 2) ? av[r].z : av[r].w;
                u64 sp; PACK2(sp, s);
                FMA2(acc[r].x, sp, ww.x);
                FMA2(acc[r].y, sp, ww.y);
            }
        }
    }
    #pragma unroll
    for (int r = 0; r < 4; ++r)
        *(ulonglong2*)(outp + (rlo + r) * HPX) = acc[r];
}

__global__ void __cluster_dims__(CSZ, 1, 1) __launch_bounds__(NTHREADS, 1)
rnn_kernel(const float* __restrict__ x,  const float* __restrict__ a0,
           const float* __restrict__ W1, const float* __restrict__ b1,
           const float* __restrict__ W2, const float* __restrict__ b2,
           float* __restrict__ out)
{
    extern __shared__ float sm[];
    float* W2s  = sm;
    float* hp   = sm + OFF_HP;
    float* hp_x = sm + OFF_HPX;
    float* a_s  = sm + OFF_AS;
    float* x2   = sm + OFF_X2;   // [2][8][128]
    float* h_s  = sm + OFF_HS;   // [8][HPX]

    const int tid   = threadIdx.x;
    const int lane  = tid & 31;
    const int wid   = tid >> 5;
    const int bx    = blockIdx.x;
    const int crank = bx & (CSZ - 1);
    const int gcl   = bx >> 2;
    const int rowbase = gcl * ROWS;
    const int jbase   = crank * 128;
    const int cj      = lane * 4;

    // ---- G1 weights into registers ----
    ulonglong2 w1x[16], w1a[16];
    {
        const float* ws = W1 + (size_t)(16 * wid) * DHID + jbase + cj;
        #pragma unroll
        for (int r = 0; r < 16; ++r)
            w1x[r] = *(const ulonglong2*)(ws + (size_t)r * DHID);
        const float* wa = W1 + (size_t)(128 + 16 * wid) * DHID + jbase + cj;
        #pragma unroll
        for (int r = 0; r < 16; ++r)
            w1a[r] = *(const ulonglong2*)(wa + (size_t)r * DHID);
    }

    // ---- prologue: W2 slice, a0, x(0)->x2[0], x(1)->x2[1], xr=x(2) ----
    for (int i = tid; i < 4096; i += NTHREADS)
        ((float4*)W2s)[i] = ((const float4*)(W2 + (size_t)jbase * DST))[i];
    for (int i = tid; i < 256; i += NTHREADS)
        ((float4*)a_s)[i] = ((const float4*)(a0 + (size_t)rowbase * DST))[i];
    for (int i = tid; i < 256; i += NTHREADS) {
        int r = i >> 5, c4 = (i & 31) << 2;
        *(float4*)(x2 + r * 128 + c4) =
            *(const float4*)(x + (size_t)(rowbase + r) * (size_t)(T_STEPS * DIN) + c4);
    }

    const int crow = wid;                 // this warp's batch row (C2/fold)
    const float4 rb2 = *(const float4*)(b2 + cj);

    // C1-j lane mapping: r8 = row, j4 = j-quad within this warp's 16-j chunk
    const int r8 = lane >> 2;
    const int j4 = lane & 3;
    const int joff = wid * 16 + j4 * 4;   // j offset within CTA slice
    const float4 rb1j = *(const float4*)(b1 + jbase + joff);
    const float* c1_rd = hp_x + r8 * HPX + joff;   // + q*HBX
    float*       c1_wr = h_s  + r8 * HPX + joff;

    const float* xrow = x + (size_t)(rowbase + crow) * (size_t)(T_STEPS * DIN) + cj;
    *(float4*)(x2 + 1024 + crow * 128 + cj) = *(const float4*)(xrow + DIN);  // x(1)
    float4 xr = *(const float4*)(xrow + 2 * DIN);                            // x(2)

    const float* g2_wr = W2s + (wid * 16) * 128 + cj;
    float* hpo  = hp   + wid * 1024 + cj;   // G2 partials, stride 128
    float* hpxo = hp_x + wid * HBX + cj;    // preact partials, stride HPX

    __syncthreads();

    // ---- G1x for step 0 ----
    gemm16_rows(x2 + wid * 16, w1x, hpxo, 0);
    gemm16_rows(x2 + wid * 16, w1x, hpxo, 4);
    __syncthreads();   // B1 (step 0 entry)

    for (int t = 0; t < T_STEPS; ++t) {
        // ---- G1a: accumulate a-part on top of G1x partials in hp_x ----
        gemm16_rows_acc(a_s + wid * 16, w1a, hpxo, 0);
        gemm16_rows_acc(a_s + wid * 16, w1a, hpxo, 4);
        __syncthreads();   // B2

        // ---- C1-j (warp-private): tree-sum 8 hp_x bufs + b1 -> tanh -> h_s ----
        {
            float4 s01 = f4add(*(const float4*)(c1_rd),
                               *(const float4*)(c1_rd + HBX));
            float4 s23 = f4add(*(const float4*)(c1_rd + 2 * HBX),
                               *(const float4*)(c1_rd + 3 * HBX));
            float4 s45 = f4add(*(const float4*)(c1_rd + 4 * HBX),
                               *(const float4*)(c1_rd + 5 * HBX));
            float4 s67 = f4add(*(const float4*)(c1_rd + 6 * HBX),
                               *(const float4*)(c1_rd + 7 * HBX));
            float4 s = f4add(f4add(s01, s23), f4add(s45, s67));
            float4 hv;
            hv.x = tanh_fast(s.x + rb1j.x);
            hv.y = tanh_fast(s.y + rb1j.y);
            hv.z = tanh_fast(s.z + rb1j.z);
            hv.w = tanh_fast(s.w + rb1j.w);
            *(float4*)(c1_wr) = hv;
        }
        __syncwarp();      // h chunk is produced and consumed by THIS warp only

        // ---- G2: same warp contracts its j-chunk; weights LDS'd once ----
        {
            ulonglong2 acc[ROWS];
            #pragma unroll
            for (int r = 0; r < ROWS; ++r) { acc[r].x = 0ull; acc[r].y = 0ull; }
            const float* act2 = h_s + wid * 16;
            #pragma unroll
            for (int kb = 0; kb < 4; ++kb) {
                float4 av[ROWS];
                #pragma unroll
                for (int r = 0; r < ROWS; ++r)
                    av[r] = *(const float4*)(act2 + r * HPX + kb * 4);
                const float* wk = g2_wr + kb * 4 * 128;
                #pragma unroll
                for (int kk = 0; kk < 4; ++kk) {
                    const ulonglong2 ww = *(const ulonglong2*)(wk + kk * 128);
                    #pragma unroll
                    for (int r = 0; r < ROWS; ++r) {
                        float s = (kk == 0) ? av[r].x : (kk == 1) ? av[r].y
                                : (kk == 2) ? av[r].z : av[r].w;
                        u64 sp; PACK2(sp, s);
                        FMA2(acc[r].x, sp, ww.x);
                        FMA2(acc[r].y, sp, ww.y);
                    }
                }
            }
            #pragma unroll
            for (int r = 0; r < ROWS; ++r)
                *(ulonglong2*)(hpo + r * 128) = acc[r];
        }
        __syncthreads();   // B4

        // ---- C2: tree-combine 8 G2 bufs -> publish my rank's partial ----
        {
            const float* hb = hp + crow * 128 + cj;
            float4 s01 = f4add(*(const float4*)(hb),
                               *(const float4*)(hb + 1024));
            float4 s23 = f4add(*(const float4*)(hb + 2048),
                               *(const float4*)(hb + 3072));
            float4 s45 = f4add(*(const float4*)(hb + 4096),
                               *(const float4*)(hb + 5120));
            float4 s67 = f4add(*(const float4*)(hb + 6144),
                               *(const float4*)(hb + 7168));
            float4 s = f4add(f4add(s01, s23), f4add(s45, s67));
            __stcg((float4*)&g_pstate[t & 1][gcl][crank][crow][cj], s);
        }
        asm volatile("barrier.cluster.arrive.aligned;" ::: "memory");

        // ---- G1x(t+1) part A: rows 0-3, hides the barrier settle ----
        const float* xb = x2 + ((t + 1) & 1) * 1024 + wid * 16;
        if (t + 1 < T_STEPS)
            gemm16_rows(xb, w1x, hpxo, 0);

        asm volatile("barrier.cluster.wait.aligned;" ::: "memory");

        // ---- fold loads (valid after wait), hidden under G1x part B ----
        float4 p0 = __ldcg((const float4*)&g_pstate[t & 1][gcl][0][crow][cj]);
        float4 p1 = __ldcg((const float4*)&g_pstate[t & 1][gcl][1][crow][cj]);
        float4 p2 = __ldcg((const float4*)&g_pstate[t & 1][gcl][2][crow][cj]);
        float4 p3 = __ldcg((const float4*)&g_pstate[t & 1][gcl][3][crow][cj]);

        if (t + 1 < T_STEPS)
            gemm16_rows(xb, w1x, hpxo, 4);

        // ---- fold combine: a(t+1) = a(t) + sum(partials) + b2 ----
        {
            float4 acc = f4add(f4add(p0, p1), f4add(p2, p3));
            float4 av = *(float4*)(a_s + crow * DST + cj);
            av.x += acc.x + rb2.x;  av.y += acc.y + rb2.y;
            av.z += acc.z + rb2.z;  av.w += acc.w + rb2.w;
            *(float4*)(a_s + crow * DST + cj) = av;
        }
        // ---- stage x(t+2); prefetch x(t+3) ----
        if (t + 2 < T_STEPS) {
            *(float4*)(x2 + (t & 1) * 1024 + crow * 128 + cj) = xr;
            if (t + 3 < T_STEPS)
                xr = *(const float4*)(xrow + (size_t)(t + 3) * DIN);
        }
        __syncthreads();   // B1
    }

    // ---- epilogue: a_s holds a(T); rank 0 writes out ----
    if (crank == 0) {
        float4 av = *(float4*)(a_s + crow * DST + cj);
        *(float4*)(out + (size_t)(rowbase + crow) * DST + cj) = av;
    }
}

extern "C" void kernel_launch(void* const* d_in, const int* in_sizes, int n_in,
                              void* d_out, int out_size) {
    const float* x  = (const float*)d_in[0];
    const float* a0 = (const float*)d_in[1];
    const float* W1 = (const float*)d_in[2];
    const float* b1 = (const float*)d_in[3];
    const float* W2 = (const float*)d_in[4];
    const float* b2 = (const float*)d_in[5];
    float* out = (float*)d_out;

    const size_t smem = SMEM_FLOATS * sizeof(float);   // 149760 B
    cudaFuncSetAttribute(rnn_kernel, cudaFuncAttributeMaxDynamicSharedMemorySize,
                         (int)smem);
    rnn_kernel<<<NCL * CSZ, NTHREADS, smem>>>(x, a0, W1, b1, W2, b2, out);
}